// round 15
// baseline (speedup 1.0000x reference)
#include <cuda_runtime.h>

#define BATCH 512
#define DLAT  32
#define ACT   18
#define FED   128
#define AED   64
#define VD    192
#define KDIM  192
#define HID   256
#define NH    32

// ---------------- scratch (static device allocations only) ----------------
__device__ __align__(16) float g_w[BATCH * DLAT];
__device__ __align__(16) float g_G[NH * DLAT * HID];
__device__ __align__(16) float g_c0[NH * HID];
__device__ __align__(16) float g_c2[NH * HID];                       // bav@W1a
__device__ __align__(16) float g_TT[NH * ACT * HID];                 // Wav@W1a, 589KB
__device__ __align__(16) float g_M[(size_t)NH * HID * HID];          // 8MB
__device__ __align__(16) float g_c1[NH * HID];

// ---------------- packed f32x2 helpers ----------------
union F2 { float2 f; unsigned long long u; };

__device__ __forceinline__ F2 ffma2(F2 a, F2 b, F2 c) {
    F2 d;
    asm("fma.rn.f32x2 %0, %1, %2, %3;" : "=l"(d.u) : "l"(a.u), "l"(b.u), "l"(c.u));
    return d;
}
__device__ __forceinline__ F2 bcast2(float x) { F2 r; r.f.x = x; r.f.y = x; return r; }
__device__ __forceinline__ F2 lds2(const float* p) { F2 r; r.u = *(const unsigned long long*)p; return r; }
__device__ __forceinline__ F2 zero2() { F2 r; r.f.x = 0.f; r.f.y = 0.f; return r; }

// ============================================================================
// K1 (prep + precompute): 416 blocks, 256 threads, 2 CTAs/SM
//   bx [0,64):    prep — 8 batches/block (1 warp each): q, softmax w, attnw
//   bx [64,128):  G[h,d,k] = Wfv[d,:]@W1[h,:128,k], c0 = bfv@W1[:128]+b1
//   bx [128,384): M[h] = W2[h]@W1o[h]  (2 kb x 4 cb x 32 h), c1 = b2@W1o+b1o
//   bx [384,416): TT[h,i,k] = Wav[i,:]@W1[h,128:,k], c2 = bav@W1[h,128:,k]
// ============================================================================
__global__ __launch_bounds__(256, 2)
void k_pre(const float* __restrict__ feat, const float* __restrict__ act,
           const float* __restrict__ Wq,   const float* __restrict__ bq,
           const float* __restrict__ Wk,   const float* __restrict__ bk,
           const float* __restrict__ Wav,  const float* __restrict__ bav,
           const float* __restrict__ Wfv,  const float* __restrict__ bfv,
           const float* __restrict__ W1,   const float* __restrict__ b1,
           const float* __restrict__ W2,   const float* __restrict__ W1o,
           const float* __restrict__ b2,   const float* __restrict__ b1o,
           float* __restrict__ out_attnw)
{
    extern __shared__ float sm[];
    int bx = blockIdx.x;
    int t  = threadIdx.x;

    if (bx < 64) {
        // ---- prep: one warp per batch ----
        float* Wk_s = sm;               // [32][193] = 6176
        float* q_s  = sm + 6176;        // [8][192]
        int wid = t >> 5, lane = t & 31;
        int b = bx * 8 + wid;

        for (int idx = t; idx < DLAT * KDIM; idx += 256) {
            int d = idx / KDIM, j = idx - d * KDIM;
            Wk_s[d * 193 + j] = Wk[idx];
        }

        float av = (lane < ACT) ? act[b * ACT + lane] : 0.f;
        float q[6];
#pragma unroll
        for (int m = 0; m < 6; m++) q[m] = bq[m * 32 + lane];
#pragma unroll
        for (int i = 0; i < ACT; i++) {
            float ai = __shfl_sync(0xffffffffu, av, i);
#pragma unroll
            for (int m = 0; m < 6; m++)
                q[m] = fmaf(ai, Wq[i * KDIM + m * 32 + lane], q[m]);
        }
#pragma unroll
        for (int m = 0; m < 6; m++) q_s[wid * 192 + m * 32 + lane] = q[m];
        __syncthreads();

        const float* qs = q_s + wid * 192;
        float s1 = 0.f;
#pragma unroll 6
        for (int j = 0; j < KDIM; j++) s1 = fmaf(Wk_s[lane * 193 + j], qs[j], s1);
        float s0 = 0.f;
#pragma unroll
        for (int m = 0; m < 6; m++) s0 = fmaf(bk[lane * 6 + m], qs[lane * 6 + m], s0);
#pragma unroll
        for (int o = 16; o > 0; o >>= 1) s0 += __shfl_xor_sync(0xffffffffu, s0, o);

        const float inv = 0.07216878364870323f; // 1/sqrt(192)
        float sc = (feat[b * DLAT + lane] * s1 + s0) * inv;
        float m = sc;
#pragma unroll
        for (int o = 16; o > 0; o >>= 1) m = fmaxf(m, __shfl_xor_sync(0xffffffffu, m, o));
        float e = __expf(sc - m);
        float s = e;
#pragma unroll
        for (int o = 16; o > 0; o >>= 1) s += __shfl_xor_sync(0xffffffffu, s, o);
        float w = e / s;
        g_w[b * DLAT + lane] = w;
#pragma unroll 8
        for (int hh = 0; hh < NH; hh++)
            out_attnw[(size_t)b * NH * DLAT + hh * DLAT + lane] = w;

    } else if (bx < 128) {
        // ---- G + c0 ----
        int bxg = bx - 64;
        int h  = bxg >> 1;
        int d0 = (bxg & 1) * 16;
        float* WfvT  = sm;              // [128 f][36 pad]
        float* bfv_s = sm + FED * 36;   // 128
        for (int r = 0; r < DLAT; r++) {
            for (int f = t; f < FED; f += 256) WfvT[f * 36 + r] = Wfv[r * FED + f];
        }
        if (t < FED) bfv_s[t] = bfv[t];
        __syncthreads();

        const float* W1h = W1 + (size_t)h * VD * HID;
        float acc[16] = {};
        float c0a = (d0 == 0) ? b1[h * HID + t] : 0.f;
#pragma unroll 4
        for (int f = 0; f < FED; f++) {
            float v = W1h[(size_t)f * HID + t];
            if (d0 == 0) c0a = fmaf(bfv_s[f], v, c0a);
            const float* wf = &WfvT[f * 36 + d0];
#pragma unroll
            for (int d = 0; d < 16; d++) acc[d] = fmaf(wf[d], v, acc[d]);
        }
#pragma unroll
        for (int d = 0; d < 16; d++)
            g_G[((size_t)h * DLAT + d0 + d) * HID + t] = acc[d];
        if (d0 == 0) g_c0[h * HID + t] = c0a;

    } else if (bx < 384) {
        // ---- M = W2 @ W1o: 2 kb x 4 cb(64) x 32 h ----
        int id = bx - 128;
        int kb = (id & 1) * 128;           // output rows
        int cb = ((id >> 1) & 3) * 64;     // output cols
        int h  = id >> 3;

        float* As = sm;              // [128][33]
        float* Bs = As + 128 * 33;   // [32][68]
        const float* Ap = W2  + (size_t)h * HID * VD;
        const float* Bp = W1o + (size_t)h * VD * HID;

        int ty = t >> 4, tx = t & 15;
        F2 acc[8][2];
#pragma unroll
        for (int r = 0; r < 8; r++)
#pragma unroll
            for (int j = 0; j < 2; j++) acc[r][j] = zero2();

        for (int vc = 0; vc < VD; vc += 32) {
            __syncthreads();
            {
                int row = t >> 5, col = t & 31;
#pragma unroll
                for (int rr = 0; rr < 16; rr++)
                    As[(row + rr * 8) * 33 + col] = Ap[(size_t)(kb + row + rr * 8) * VD + vc + col];
            }
#pragma unroll
            for (int i = 0; i < 8; i++) {
                int idx = t + i * 256;
                int vr = idx >> 6, col = idx & 63;
                Bs[vr * 68 + col] = Bp[(size_t)(vc + vr) * HID + cb + col];
            }
            __syncthreads();
#pragma unroll
            for (int v = 0; v < 32; v++) {
                F2 bvec[2];
#pragma unroll
                for (int j = 0; j < 2; j++) bvec[j] = lds2(&Bs[v * 68 + tx * 2 + 32 * j]);
#pragma unroll
                for (int r = 0; r < 8; r++) {
                    F2 a2 = bcast2(As[(ty * 8 + r) * 33 + v]);
#pragma unroll
                    for (int j = 0; j < 2; j++) acc[r][j] = ffma2(a2, bvec[j], acc[r][j]);
                }
            }
        }

        float* Mp = g_M + (size_t)h * HID * HID;
#pragma unroll
        for (int r = 0; r < 8; r++)
#pragma unroll
            for (int j = 0; j < 2; j++)
                *(unsigned long long*)&Mp[(size_t)(kb + ty * 8 + r) * HID + cb + tx * 2 + 32 * j] = acc[r][j].u;

        if ((id & 1) == 0 && t < 64) {
            int kp = cb + t;
            float c = b1o[h * HID + kp];
            for (int v = 0; v < VD; v++)
                c = fmaf(b2[h * VD + v], Bp[(size_t)v * HID + kp], c);
            g_c1[h * HID + kp] = c;
        }

    } else {
        // ---- TT[h,i,k] = sum_a Wav[i,a] W1a[h,a,k];  c2 = sum_a bav[a] W1a ----
        int h = bx - 384;
        float* WavS = sm;               // [18][64] = 1152
        float* bavS = sm + 1152;        // 64
        for (int idx = t; idx < ACT * AED; idx += 256) WavS[idx] = Wav[idx];
        if (t < AED) bavS[t] = bav[t];
        __syncthreads();

        const float* W1a = W1 + (size_t)h * VD * HID + (size_t)FED * HID;
        float acc[ACT] = {};
        float c2 = 0.f;
#pragma unroll 2
        for (int a = 0; a < AED; a++) {
            float v = W1a[(size_t)a * HID + t];        // coalesced LDG
            c2 = fmaf(bavS[a], v, c2);
#pragma unroll
            for (int i = 0; i < ACT; i++)
                acc[i] = fmaf(WavS[i * AED + a], v, acc[i]);
        }
#pragma unroll
        for (int i = 0; i < ACT; i++)
            g_TT[((size_t)h * ACT + i) * HID + t] = acc[i];
        g_c2[h * HID + t] = c2;
    }
}

// ============================================================================
// K2 (fused E+pool+out): grid (8, 32), 256 threads, 2 CTAs/SM.  (R14 winner)
// Phase 1: e0 = act@TT (rank-18) + c0 + c2; P = sum_d w*relu(z*G + e0).
// Phase 2: GEMM P[64,256] @ M[256,256], dbl-buffered 16-row M chunks.
// smem: P 16384 | R 8448 (Gb 2048 + zw 4096 + TTp 1152 + actS 1152
//       <-> ph2 M dblbuf 2x4096) | cw 512 | c0 256 = 25600f = 102400B
// ============================================================================
__global__ __launch_bounds__(256, 2)
void k_fused(const float* __restrict__ feat, const float* __restrict__ act,
             const float* __restrict__ W2o,  const float* __restrict__ b2o,
             float* __restrict__ effect)
{
    int h  = blockIdx.y;
    int b0 = blockIdx.x * 64;
    int t  = threadIdx.x;
    int tb = t >> 4, tk = t & 15;     // 16 row-groups x 16 lanes

    extern __shared__ float sm[];
    float* P_s  = sm;                 // [64][256]
    float* R    = sm + 16384;         // 8448f overlay
    float* Gb   = R;                  // ph1: Gbuf [32][64]   (2048f)
    float* zw   = R + 2048;           // ph1: zw [64][32] f2  (4096f)
    float* TTp  = R + 6144;           // ph1: TT slice [18][64] (1152f)
    float* actS = R + 7296;           // ph1: act [64][18]    (1152f)
    float* cw   = sm + 16384 + 8448;  // ph2: c1 [256] + W2o [256]
    float* c0s  = cw + 512;           // c0 + c2 [256]

    // ---- phase 1 static loads ----
    for (int idx = t; idx < 64 * DLAT; idx += 256) {
        int row = idx >> 5, d = idx & 31;
        zw[idx * 2 + 0] = feat[(b0 + row) * DLAT + d];
        zw[idx * 2 + 1] = g_w[(b0 + row) * DLAT + d];
    }
    for (int idx = t; idx < 64 * ACT; idx += 256) {
        int row = idx / ACT, i = idx - row * ACT;
        actS[idx] = act[(b0 + row) * ACT + i];
    }
    if (t < HID) c0s[t] = g_c0[h * HID + t] + g_c2[h * HID + t];

    const float* Gp  = g_G  + (size_t)h * DLAT * HID;
    const float* TTh = g_TT + (size_t)h * ACT * HID;

    // ---- phase 1: 4 column passes of 64 cols ----
#pragma unroll 1
    for (int p = 0; p < 4; p++) {
        int cb = p * 64;
        __syncthreads();
#pragma unroll
        for (int i = 0; i < 2; i++) {          // Gbuf: 512 float4 / 256 thr
            int idx = t + i * 256;
            int d = idx >> 4, c4 = idx & 15;
            ((float4*)Gb)[idx] = *(const float4*)&Gp[d * HID + cb + c4 * 4];
        }
        {                                       // TT slice: 288 float4
            int idx = t;
            int ii = idx >> 4, c4 = idx & 15;
            ((float4*)TTp)[idx] = *(const float4*)&TTh[(size_t)ii * HID + cb + c4 * 4];
            idx = t + 256;
            if (idx < ACT * 16) {
                ii = idx >> 4; c4 = idx & 15;
                ((float4*)TTp)[idx] = *(const float4*)&TTh[(size_t)ii * HID + cb + c4 * 4];
            }
        }
        __syncthreads();

        int lc = tk * 2;
        // e0 = c0+c2 + act @ TT  (rank-18)
        F2 e0[4][2], acc[4][2];
#pragma unroll
        for (int r = 0; r < 4; r++)
#pragma unroll
            for (int i = 0; i < 2; i++) {
                e0[r][i] = lds2(&c0s[cb + lc + 32 * i]);
                acc[r][i] = zero2();
            }
#pragma unroll 2
        for (int ii = 0; ii < ACT; ii++) {
            F2 tt[2];
#pragma unroll
            for (int i = 0; i < 2; i++) tt[i] = lds2(&TTp[ii * 64 + lc + 32 * i]);
#pragma unroll
            for (int r = 0; r < 4; r++) {
                F2 av = bcast2(actS[(tb * 4 + r) * ACT + ii]);
#pragma unroll
                for (int i = 0; i < 2; i++) e0[r][i] = ffma2(av, tt[i], e0[r][i]);
            }
        }

#pragma unroll 4
        for (int d = 0; d < DLAT; d++) {
            F2 gr[2];
#pragma unroll
            for (int i = 0; i < 2; i++) gr[i] = lds2(&Gb[d * 64 + lc + 32 * i]);
#pragma unroll
            for (int r = 0; r < 4; r++) {
                float2 z = *(const float2*)&zw[((tb * 4 + r) * DLAT + d) * 2];
                F2 z2 = bcast2(z.x), w2 = bcast2(z.y);
#pragma unroll
                for (int i = 0; i < 2; i++) {
                    F2 u = ffma2(z2, gr[i], e0[r][i]);
                    u.f.x = fmaxf(u.f.x, 0.f);
                    u.f.y = fmaxf(u.f.y, 0.f);
                    acc[r][i] = ffma2(w2, u, acc[r][i]);
                }
            }
        }

#pragma unroll
        for (int r = 0; r < 4; r++)
#pragma unroll
            for (int i = 0; i < 2; i++)
                *(unsigned long long*)&P_s[(tb * 4 + r) * HID + cb + lc + 32 * i] = acc[r][i].u;
    }
    __syncthreads();   // phase 1 done; R free

    // ---- phase 2 loads: c1 + W2o, M chunk 0 into R[0] ----
    if (t < HID) {
        cw[t]       = g_c1[h * HID + t];
        cw[HID + t] = W2o[h * HID + t];
    }
    const float* Mp = g_M + (size_t)h * HID * HID;
#pragma unroll
    for (int i = 0; i < 4; i++)        // chunk 0: 16 rows = 1024 float4
        ((float4*)R)[t + i * 256] = ((const float4*)Mp)[t + i * 256];
    __syncthreads();

    // ---- phase 2: GEMM, 16 k-chunks, dbl-buffered (1 sync/chunk) ----
    F2 acc[4][8];
#pragma unroll
    for (int r = 0; r < 4; r++)
#pragma unroll
        for (int j = 0; j < 8; j++) acc[r][j] = zero2();

#pragma unroll 1
    for (int kc = 0; kc < 16; kc++) {
        float4 pf[4];
        if (kc < 15) {
#pragma unroll
            for (int i = 0; i < 4; i++)
                pf[i] = ((const float4*)(Mp + (size_t)(kc + 1) * 16 * HID))[t + i * 256];
        }
        const float* Mc = R + (kc & 1) * 4096;
#pragma unroll
        for (int kk = 0; kk < 16; kk++) {
            int k = kc * 16 + kk;
            F2 mv[8];
#pragma unroll
            for (int j = 0; j < 8; j++) mv[j] = lds2(&Mc[kk * HID + tk * 2 + 32 * j]);
#pragma unroll
            for (int r = 0; r < 4; r++) {
                F2 p2 = bcast2(P_s[(tb * 4 + r) * HID + k]);
#pragma unroll
                for (int j = 0; j < 8; j++) acc[r][j] = ffma2(p2, mv[j], acc[r][j]);
            }
        }
        if (kc < 15) {
            float* dst = R + ((kc + 1) & 1) * 4096;
#pragma unroll
            for (int i = 0; i < 4; i++)
                ((float4*)dst)[t + i * 256] = pf[i];
        }
        __syncthreads();
    }

    // ---- epilogue: +c1, relu, dot W2o, reduce over tk (16 lanes) ----
    float part[4];
#pragma unroll
    for (int r = 0; r < 4; r++) {
        float s = 0.f;
#pragma unroll
        for (int j = 0; j < 8; j++) {
            int c = tk * 2 + 32 * j;
            float hx = fmaxf(acc[r][j].f.x + cw[c], 0.f);
            float hy = fmaxf(acc[r][j].f.y + cw[c + 1], 0.f);
            s = fmaf(hx, cw[HID + c], s);
            s = fmaf(hy, cw[HID + c + 1], s);
        }
        part[r] = s;
    }
#pragma unroll
    for (int o = 8; o > 0; o >>= 1)
#pragma unroll
        for (int r = 0; r < 4; r++)
            part[r] += __shfl_xor_sync(0xffffffffu, part[r], o);

    if (tk == 0) {
        float bo = b2o[h];
#pragma unroll
        for (int r = 0; r < 4; r++)
            effect[(size_t)(b0 + tb * 4 + r) * NH + h] = part[r] + bo;
    }
}

// ============================================================================
extern "C" void kernel_launch(void* const* d_in, const int* in_sizes, int n_in,
                              void* d_out, int out_size)
{
    const float* feat = (const float*)d_in[0];
    const float* act  = (const float*)d_in[1];
    const float* Wq   = (const float*)d_in[2];
    const float* bq   = (const float*)d_in[3];
    const float* Wk   = (const float*)d_in[4];
    const float* bk   = (const float*)d_in[5];
    const float* Wav  = (const float*)d_in[6];
    const float* bav  = (const float*)d_in[7];
    const float* Wfv  = (const float*)d_in[8];
    const float* bfv  = (const float*)d_in[9];
    const float* W1   = (const float*)d_in[10];
    const float* b1   = (const float*)d_in[11];
    const float* W2   = (const float*)d_in[12];
    const float* b2   = (const float*)d_in[13];
    const float* W1o  = (const float*)d_in[14];
    const float* b1o  = (const float*)d_in[15];
    const float* W2o  = (const float*)d_in[16];
    const float* b2o  = (const float*)d_in[17];

    float* out    = (float*)d_out;
    float* effect = out;                    // [B, H]
    float* attnw  = out + BATCH * NH;       // [B, H, D]

    int smem1 = (6176 + 8 * 192) * 4;                            // 30848 (prep = max)
    int smem2 = (16384 + 8448 + 512 + 256) * 4;                  // 102400
    cudaFuncSetAttribute(k_pre,   cudaFuncAttributeMaxDynamicSharedMemorySize, smem1);
    cudaFuncSetAttribute(k_fused, cudaFuncAttributeMaxDynamicSharedMemorySize, smem2);

    k_pre<<<416, 256, smem1>>>(feat, act, Wq, bq, Wk, bk, Wav, bav,
                               Wfv, bfv, W1, b1, W2, W1o, b2, b1o, attnw);
    k_fused<<<dim3(BATCH / 64, NH), 256, smem2>>>(feat, act, W2o, b2o, effect);
}

// round 16
// speedup vs baseline: 1.0295x; 1.0295x over previous
#include <cuda_runtime.h>

#define BATCH 512
#define DLAT  32
#define ACT   18
#define FED   128
#define AED   64
#define VD    192
#define KDIM  192
#define HID   256
#define NH    32

// ---------------- scratch (static device allocations only) ----------------
__device__ __align__(16) float g_w[BATCH * DLAT];
__device__ __align__(16) float g_G[NH * DLAT * HID];
__device__ __align__(16) float g_c0[NH * HID];
__device__ __align__(16) float g_c2[NH * HID];                       // bav@W1a
__device__ __align__(16) float g_TT[NH * ACT * HID];                 // Wav@W1a, 589KB
__device__ __align__(16) float g_M[(size_t)NH * HID * HID];          // 8MB
__device__ __align__(16) float g_c1[NH * HID];

// ---------------- packed f32x2 helpers ----------------
union F2 { float2 f; unsigned long long u; };

__device__ __forceinline__ F2 ffma2(F2 a, F2 b, F2 c) {
    F2 d;
    asm("fma.rn.f32x2 %0, %1, %2, %3;" : "=l"(d.u) : "l"(a.u), "l"(b.u), "l"(c.u));
    return d;
}
__device__ __forceinline__ F2 bcast2(float x) { F2 r; r.f.x = x; r.f.y = x; return r; }
__device__ __forceinline__ F2 lds2(const float* p) { F2 r; r.u = *(const unsigned long long*)p; return r; }
__device__ __forceinline__ F2 zero2() { F2 r; r.f.x = 0.f; r.f.y = 0.f; return r; }

__device__ __forceinline__ void cp_async16(unsigned smem_dst, const float* gsrc) {
    asm volatile("cp.async.cg.shared.global [%0], [%1], 16;"
                 :: "r"(smem_dst), "l"(gsrc));
}

// ============================================================================
// K1 (prep + precompute): 288 blocks (one wave at 2 CTAs/SM), 256 threads
//   bx [0,64):    prep — 8 batches/block (1 warp each): q, softmax w, attnw
//   bx [64,128):  G[h,d,k] = Wfv[d,:]@W1[h,:128,k], c0 = bfv@W1[:128]+b1
//   bx [128,256): M[h] = W2[h]@W1o[h], c1 = b2@W1o + b1o
//   bx [256,288): TT[h,i,k] = Wav[i,:]@W1[h,128:,k], c2 = bav@W1[h,128:,k]
// ============================================================================
__global__ __launch_bounds__(256, 2)
void k_pre(const float* __restrict__ feat, const float* __restrict__ act,
           const float* __restrict__ Wq,   const float* __restrict__ bq,
           const float* __restrict__ Wk,   const float* __restrict__ bk,
           const float* __restrict__ Wav,  const float* __restrict__ bav,
           const float* __restrict__ Wfv,  const float* __restrict__ bfv,
           const float* __restrict__ W1,   const float* __restrict__ b1,
           const float* __restrict__ W2,   const float* __restrict__ W1o,
           const float* __restrict__ b2,   const float* __restrict__ b1o,
           float* __restrict__ out_attnw)
{
    extern __shared__ float sm[];
    int bx = blockIdx.x;
    int t  = threadIdx.x;

    if (bx < 64) {
        // ---- prep: one warp per batch ----
        float* Wk_s = sm;               // [32][193] = 6176
        float* q_s  = sm + 6176;        // [8][192]
        int wid = t >> 5, lane = t & 31;
        int b = bx * 8 + wid;

        for (int idx = t; idx < DLAT * KDIM; idx += 256) {
            int d = idx / KDIM, j = idx - d * KDIM;
            Wk_s[d * 193 + j] = Wk[idx];
        }

        float av = (lane < ACT) ? act[b * ACT + lane] : 0.f;
        float q[6];
#pragma unroll
        for (int m = 0; m < 6; m++) q[m] = bq[m * 32 + lane];
#pragma unroll
        for (int i = 0; i < ACT; i++) {
            float ai = __shfl_sync(0xffffffffu, av, i);
#pragma unroll
            for (int m = 0; m < 6; m++)
                q[m] = fmaf(ai, Wq[i * KDIM + m * 32 + lane], q[m]);
        }
#pragma unroll
        for (int m = 0; m < 6; m++) q_s[wid * 192 + m * 32 + lane] = q[m];
        __syncthreads();

        const float* qs = q_s + wid * 192;
        float s1 = 0.f;
#pragma unroll 6
        for (int j = 0; j < KDIM; j++) s1 = fmaf(Wk_s[lane * 193 + j], qs[j], s1);
        float s0 = 0.f;
#pragma unroll
        for (int m = 0; m < 6; m++) s0 = fmaf(bk[lane * 6 + m], qs[lane * 6 + m], s0);
#pragma unroll
        for (int o = 16; o > 0; o >>= 1) s0 += __shfl_xor_sync(0xffffffffu, s0, o);

        const float inv = 0.07216878364870323f; // 1/sqrt(192)
        float sc = (feat[b * DLAT + lane] * s1 + s0) * inv;
        float m = sc;
#pragma unroll
        for (int o = 16; o > 0; o >>= 1) m = fmaxf(m, __shfl_xor_sync(0xffffffffu, m, o));
        float e = __expf(sc - m);
        float s = e;
#pragma unroll
        for (int o = 16; o > 0; o >>= 1) s += __shfl_xor_sync(0xffffffffu, s, o);
        float w = e / s;
        g_w[b * DLAT + lane] = w;
#pragma unroll 8
        for (int hh = 0; hh < NH; hh++)
            out_attnw[(size_t)b * NH * DLAT + hh * DLAT + lane] = w;

    } else if (bx < 128) {
        // ---- G + c0 ----
        int bxg = bx - 64;
        int h  = bxg >> 1;
        int d0 = (bxg & 1) * 16;
        float* WfvT  = sm;              // [128 f][36 pad]
        float* bfv_s = sm + FED * 36;   // 128
        for (int r = 0; r < DLAT; r++) {
            for (int f = t; f < FED; f += 256) WfvT[f * 36 + r] = Wfv[r * FED + f];
        }
        if (t < FED) bfv_s[t] = bfv[t];
        __syncthreads();

        const float* W1h = W1 + (size_t)h * VD * HID;
        float acc[16] = {};
        float c0a = (d0 == 0) ? b1[h * HID + t] : 0.f;
#pragma unroll 4
        for (int f = 0; f < FED; f++) {
            float v = W1h[(size_t)f * HID + t];
            if (d0 == 0) c0a = fmaf(bfv_s[f], v, c0a);
            const float* wf = &WfvT[f * 36 + d0];
#pragma unroll
            for (int d = 0; d < 16; d++) acc[d] = fmaf(wf[d], v, acc[d]);
        }
#pragma unroll
        for (int d = 0; d < 16; d++)
            g_G[((size_t)h * DLAT + d0 + d) * HID + t] = acc[d];
        if (d0 == 0) g_c0[h * HID + t] = c0a;

    } else if (bx < 256) {
        // ---- M = W2 @ W1o, c1 ----
        int id = bx - 128;
        int kb = (id & 1) * 128;
        int cb = ((id >> 1) & 1) * 128;
        int h  = id >> 2;

        float* As = sm;              // [128][33]
        float* Bs = As + 128 * 33;   // [32][132]
        const float* Ap = W2  + (size_t)h * HID * VD;
        const float* Bp = W1o + (size_t)h * VD * HID;

        int ty = t >> 4, tx = t & 15;
        F2 acc[8][4];
#pragma unroll
        for (int r = 0; r < 8; r++)
#pragma unroll
            for (int j = 0; j < 4; j++) acc[r][j] = zero2();

        for (int vc = 0; vc < VD; vc += 32) {
            __syncthreads();
            {
                int row = t >> 5, col = t & 31;
#pragma unroll
                for (int rr = 0; rr < 16; rr++)
                    As[(row + rr * 8) * 33 + col] = Ap[(size_t)(kb + row + rr * 8) * VD + vc + col];
            }
#pragma unroll
            for (int i = 0; i < 16; i++) {
                int idx = t + i * 256;
                int vr = idx >> 7, col = idx & 127;
                Bs[vr * 132 + col] = Bp[(size_t)(vc + vr) * HID + cb + col];
            }
            __syncthreads();
#pragma unroll
            for (int v = 0; v < 32; v++) {
                F2 bvec[4];
#pragma unroll
                for (int j = 0; j < 4; j++) bvec[j] = lds2(&Bs[v * 132 + tx * 2 + 32 * j]);
#pragma unroll
                for (int r = 0; r < 8; r++) {
                    F2 a2 = bcast2(As[(ty * 8 + r) * 33 + v]);
#pragma unroll
                    for (int j = 0; j < 4; j++) acc[r][j] = ffma2(a2, bvec[j], acc[r][j]);
                }
            }
        }

        float* Mp = g_M + (size_t)h * HID * HID;
#pragma unroll
        for (int r = 0; r < 8; r++)
#pragma unroll
            for (int j = 0; j < 4; j++)
                *(unsigned long long*)&Mp[(size_t)(kb + ty * 8 + r) * HID + cb + tx * 2 + 32 * j] = acc[r][j].u;

        if ((id & 1) == 0 && t < 128) {
            int kp = cb + t;
            float c = b1o[h * HID + kp];
            for (int v = 0; v < VD; v++)
                c = fmaf(b2[h * VD + v], Bp[(size_t)v * HID + kp], c);
            g_c1[h * HID + kp] = c;
        }

    } else {
        // ---- TT[h,i,k] = sum_a Wav[i,a] W1a[h,a,k];  c2 = sum_a bav[a] W1a ----
        int h = bx - 256;
        float* WavS = sm;               // [18][64] = 1152
        float* bavS = sm + 1152;        // 64
        for (int idx = t; idx < ACT * AED; idx += 256) WavS[idx] = Wav[idx];
        if (t < AED) bavS[t] = bav[t];
        __syncthreads();

        const float* W1a = W1 + (size_t)h * VD * HID + (size_t)FED * HID;
        float acc[ACT] = {};
        float c2 = 0.f;
#pragma unroll 2
        for (int a = 0; a < AED; a++) {
            float v = W1a[(size_t)a * HID + t];        // coalesced LDG
            c2 = fmaf(bavS[a], v, c2);
#pragma unroll
            for (int i = 0; i < ACT; i++)
                acc[i] = fmaf(WavS[i * AED + a], v, acc[i]);
        }
#pragma unroll
        for (int i = 0; i < ACT; i++)
            g_TT[((size_t)h * ACT + i) * HID + t] = acc[i];
        g_c2[h * HID + t] = c2;
    }
}

// ============================================================================
// K2 (fused E+pool+out): grid (8, 32), 256 threads, 2 CTAs/SM.  (R14 base)
// Phase 1: e0 = act@TT (rank-18) + c0 + c2; P = sum_d w*relu(z*G + e0).
// Phase 2: GEMM P[64,256] @ M[256,256], dbl-buffered 16-row M chunks with
//          cp.async prefetch (no regs held, no STS phase) and paired P
//          broadcasts (1 LDS.64 per 2 kk per row).
// smem: P 16384 | R 8448 (Gb 2048 + zw 4096 + TTp 1152 + actS 1152
//       <-> ph2 M dblbuf 2x4096) | cw 512 | c0 256 = 25600f = 102400B
// ============================================================================
__global__ __launch_bounds__(256, 2)
void k_fused(const float* __restrict__ feat, const float* __restrict__ act,
             const float* __restrict__ W2o,  const float* __restrict__ b2o,
             float* __restrict__ effect)
{
    int h  = blockIdx.y;
    int b0 = blockIdx.x * 64;
    int t  = threadIdx.x;
    int tb = t >> 4, tk = t & 15;     // 16 row-groups x 16 lanes

    extern __shared__ float sm[];
    float* P_s  = sm;                 // [64][256]
    float* R    = sm + 16384;         // 8448f overlay
    float* Gb   = R;                  // ph1: Gbuf [32][64]   (2048f)
    float* zw   = R + 2048;           // ph1: zw [64][32] f2  (4096f)
    float* TTp  = R + 6144;           // ph1: TT slice [18][64] (1152f)
    float* actS = R + 7296;           // ph1: act [64][18]    (1152f)
    float* cw   = sm + 16384 + 8448;  // ph2: c1 [256] + W2o [256]
    float* c0s  = cw + 512;           // c0 + c2 [256]

    // ---- phase 1 static loads ----
    for (int idx = t; idx < 64 * DLAT; idx += 256) {
        int row = idx >> 5, d = idx & 31;
        zw[idx * 2 + 0] = feat[(b0 + row) * DLAT + d];
        zw[idx * 2 + 1] = g_w[(b0 + row) * DLAT + d];
    }
    for (int idx = t; idx < 64 * ACT; idx += 256) {
        int row = idx / ACT, i = idx - row * ACT;
        actS[idx] = act[(b0 + row) * ACT + i];
    }
    if (t < HID) c0s[t] = g_c0[h * HID + t] + g_c2[h * HID + t];

    const float* Gp  = g_G  + (size_t)h * DLAT * HID;
    const float* TTh = g_TT + (size_t)h * ACT * HID;

    // ---- phase 1: 4 column passes of 64 cols ----
#pragma unroll 1
    for (int p = 0; p < 4; p++) {
        int cb = p * 64;
        __syncthreads();
#pragma unroll
        for (int i = 0; i < 2; i++) {          // Gbuf: 512 float4 / 256 thr
            int idx = t + i * 256;
            int d = idx >> 4, c4 = idx & 15;
            ((float4*)Gb)[idx] = *(const float4*)&Gp[d * HID + cb + c4 * 4];
        }
        {                                       // TT slice: 288 float4
            int idx = t;
            int ii = idx >> 4, c4 = idx & 15;
            ((float4*)TTp)[idx] = *(const float4*)&TTh[(size_t)ii * HID + cb + c4 * 4];
            idx = t + 256;
            if (idx < ACT * 16) {
                ii = idx >> 4; c4 = idx & 15;
                ((float4*)TTp)[idx] = *(const float4*)&TTh[(size_t)ii * HID + cb + c4 * 4];
            }
        }
        __syncthreads();

        int lc = tk * 2;
        // e0 = c0+c2 + act @ TT  (rank-18)
        F2 e0[4][2], acc[4][2];
#pragma unroll
        for (int r = 0; r < 4; r++)
#pragma unroll
            for (int i = 0; i < 2; i++) {
                e0[r][i] = lds2(&c0s[cb + lc + 32 * i]);
                acc[r][i] = zero2();
            }
#pragma unroll 2
        for (int ii = 0; ii < ACT; ii++) {
            F2 tt[2];
#pragma unroll
            for (int i = 0; i < 2; i++) tt[i] = lds2(&TTp[ii * 64 + lc + 32 * i]);
#pragma unroll
            for (int r = 0; r < 4; r++) {
                F2 av = bcast2(actS[(tb * 4 + r) * ACT + ii]);
#pragma unroll
                for (int i = 0; i < 2; i++) e0[r][i] = ffma2(av, tt[i], e0[r][i]);
            }
        }

#pragma unroll 4
        for (int d = 0; d < DLAT; d++) {
            F2 gr[2];
#pragma unroll
            for (int i = 0; i < 2; i++) gr[i] = lds2(&Gb[d * 64 + lc + 32 * i]);
#pragma unroll
            for (int r = 0; r < 4; r++) {
                float2 z = *(const float2*)&zw[((tb * 4 + r) * DLAT + d) * 2];
                F2 z2 = bcast2(z.x), w2 = bcast2(z.y);
#pragma unroll
                for (int i = 0; i < 2; i++) {
                    F2 u = ffma2(z2, gr[i], e0[r][i]);
                    u.f.x = fmaxf(u.f.x, 0.f);
                    u.f.y = fmaxf(u.f.y, 0.f);
                    acc[r][i] = ffma2(w2, u, acc[r][i]);
                }
            }
        }

#pragma unroll
        for (int r = 0; r < 4; r++)
#pragma unroll
            for (int i = 0; i < 2; i++)
                *(unsigned long long*)&P_s[(tb * 4 + r) * HID + cb + lc + 32 * i] = acc[r][i].u;
    }
    __syncthreads();   // phase 1 done; R free

    // ---- phase 2 loads: c1 + W2o; M chunk 0 via cp.async into R[0] ----
    if (t < HID) {
        cw[t]       = g_c1[h * HID + t];
        cw[HID + t] = W2o[h * HID + t];
    }
    const float* Mp = g_M + (size_t)h * HID * HID;
    unsigned Rsh = (unsigned)__cvta_generic_to_shared(R);
#pragma unroll
    for (int i = 0; i < 4; i++) {       // chunk 0: 1024 float4 / 256 thr
        int idx = t + i * 256;
        cp_async16(Rsh + idx * 16, Mp + idx * 4);
    }
    asm volatile("cp.async.commit_group;");
    asm volatile("cp.async.wait_group 0;" ::: "memory");
    __syncthreads();

    // ---- phase 2: GEMM, 16 k-chunks, dbl-buffered via cp.async ----
    F2 acc[4][8];
#pragma unroll
    for (int r = 0; r < 4; r++)
#pragma unroll
        for (int j = 0; j < 8; j++) acc[r][j] = zero2();

#pragma unroll 1
    for (int kc = 0; kc < 16; kc++) {
        if (kc < 15) {
            unsigned dst = Rsh + (((kc + 1) & 1) * 4096) * 4;
            const float* src = Mp + (size_t)(kc + 1) * 16 * HID;
#pragma unroll
            for (int i = 0; i < 4; i++) {
                int idx = t + i * 256;
                cp_async16(dst + idx * 16, src + idx * 4);
            }
            asm volatile("cp.async.commit_group;");
        }
        const float* Mc = R + (kc & 1) * 4096;
#pragma unroll
        for (int kk2 = 0; kk2 < 8; kk2++) {
            // P broadcasts: one LDS.64 per row covers 2 consecutive kk
            F2 pr[4];
#pragma unroll
            for (int r = 0; r < 4; r++)
                pr[r] = lds2(&P_s[(tb * 4 + r) * HID + kc * 16 + kk2 * 2]);
#pragma unroll
            for (int u = 0; u < 2; u++) {
                int kk = kk2 * 2 + u;
                F2 mv[8];
#pragma unroll
                for (int j = 0; j < 8; j++) mv[j] = lds2(&Mc[kk * HID + tk * 2 + 32 * j]);
#pragma unroll
                for (int r = 0; r < 4; r++) {
                    F2 p2 = bcast2(u == 0 ? pr[r].f.x : pr[r].f.y);
#pragma unroll
                    for (int j = 0; j < 8; j++) acc[r][j] = ffma2(p2, mv[j], acc[r][j]);
                }
            }
        }
        if (kc < 15)
            asm volatile("cp.async.wait_group 0;" ::: "memory");
        __syncthreads();
    }

    // ---- epilogue: +c1, relu, dot W2o, reduce over tk (16 lanes) ----
    float part[4];
#pragma unroll
    for (int r = 0; r < 4; r++) {
        float s = 0.f;
#pragma unroll
        for (int j = 0; j < 8; j++) {
            int c = tk * 2 + 32 * j;
            float hx = fmaxf(acc[r][j].f.x + cw[c], 0.f);
            float hy = fmaxf(acc[r][j].f.y + cw[c + 1], 0.f);
            s = fmaf(hx, cw[HID + c], s);
            s = fmaf(hy, cw[HID + c + 1], s);
        }
        part[r] = s;
    }
#pragma unroll
    for (int o = 8; o > 0; o >>= 1)
#pragma unroll
        for (int r = 0; r < 4; r++)
            part[r] += __shfl_xor_sync(0xffffffffu, part[r], o);

    if (tk == 0) {
        float bo = b2o[h];
#pragma unroll
        for (int r = 0; r < 4; r++)
            effect[(size_t)(b0 + tb * 4 + r) * NH + h] = part[r] + bo;
    }
}

// ============================================================================
extern "C" void kernel_launch(void* const* d_in, const int* in_sizes, int n_in,
                              void* d_out, int out_size)
{
    const float* feat = (const float*)d_in[0];
    const float* act  = (const float*)d_in[1];
    const float* Wq   = (const float*)d_in[2];
    const float* bq   = (const float*)d_in[3];
    const float* Wk   = (const float*)d_in[4];
    const float* bk   = (const float*)d_in[5];
    const float* Wav  = (const float*)d_in[6];
    const float* bav  = (const float*)d_in[7];
    const float* Wfv  = (const float*)d_in[8];
    const float* bfv  = (const float*)d_in[9];
    const float* W1   = (const float*)d_in[10];
    const float* b1   = (const float*)d_in[11];
    const float* W2   = (const float*)d_in[12];
    const float* b2   = (const float*)d_in[13];
    const float* W1o  = (const float*)d_in[14];
    const float* b1o  = (const float*)d_in[15];
    const float* W2o  = (const float*)d_in[16];
    const float* b2o  = (const float*)d_in[17];

    float* out    = (float*)d_out;
    float* effect = out;                    // [B, H]
    float* attnw  = out + BATCH * NH;       // [B, H, D]

    int smem1 = (128 * 33 + 32 * 132) * 4;                       // 33792 (M branch = max)
    int smem2 = (16384 + 8448 + 512 + 256) * 4;                  // 102400
    cudaFuncSetAttribute(k_pre,   cudaFuncAttributeMaxDynamicSharedMemorySize, smem1);
    cudaFuncSetAttribute(k_fused, cudaFuncAttributeMaxDynamicSharedMemorySize, smem2);

    k_pre<<<288, 256, smem1>>>(feat, act, Wq, bq, Wk, bk, Wav, bav,
                               Wfv, bfv, W1, b1, W2, W1o, b2, b1o, attnw);
    k_fused<<<dim3(BATCH / 64, NH), 256, smem2>>>(feat, act, W2o, b2o, effect);
}

// round 17
// speedup vs baseline: 1.0511x; 1.0210x over previous
#include <cuda_runtime.h>

#define BATCH 512
#define DLAT  32
#define ACT   18
#define FED   128
#define AED   64
#define VD    192
#define KDIM  192
#define HID   256
#define NH    32

// ---------------- scratch (static device allocations only) ----------------
__device__ __align__(16) float g_w[BATCH * DLAT];
__device__ __align__(16) float g_G[NH * DLAT * HID];
__device__ __align__(16) float g_c0[NH * HID];
__device__ __align__(16) float g_c2[NH * HID];                       // bav@W1a
__device__ __align__(16) float g_TT[NH * ACT * HID];                 // Wav@W1a, 589KB
__device__ __align__(16) float g_M[(size_t)NH * HID * HID];          // 8MB
__device__ __align__(16) float g_c1[NH * HID];

// ---------------- packed f32x2 helpers ----------------
union F2 { float2 f; unsigned long long u; };

__device__ __forceinline__ F2 ffma2(F2 a, F2 b, F2 c) {
    F2 d;
    asm("fma.rn.f32x2 %0, %1, %2, %3;" : "=l"(d.u) : "l"(a.u), "l"(b.u), "l"(c.u));
    return d;
}
__device__ __forceinline__ F2 bcast2(float x) { F2 r; r.f.x = x; r.f.y = x; return r; }
__device__ __forceinline__ F2 lds2(const float* p) { F2 r; r.u = *(const unsigned long long*)p; return r; }
__device__ __forceinline__ F2 zero2() { F2 r; r.f.x = 0.f; r.f.y = 0.f; return r; }

// ============================================================================
// K1 (prep + precompute): 288 blocks (one wave at 2 CTAs/SM), 256 threads.
// BLOCK ORDER CHOSEN FOR PLACEMENT: the heavy M-GEMM blocks are bids 0..127,
// so bid%148 gives each M block its own SM (slot 1); all short branches land
// in the other slot and overlap.
//   bx [0,128):   M[h] = W2[h]@W1o[h], c1 = b2@W1o + b1o
//   bx [128,192): prep — 8 batches/block (1 warp each): q, softmax w, attnw
//   bx [192,256): G[h,d,k] = Wfv[d,:]@W1[h,:128,k], c0 = bfv@W1[:128]+b1
//   bx [256,288): TT[h,i,k] = Wav[i,:]@W1[h,128:,k], c2 = bav@W1[h,128:,k]
// ============================================================================
__global__ __launch_bounds__(256, 2)
void k_pre(const float* __restrict__ feat, const float* __restrict__ act,
           const float* __restrict__ Wq,   const float* __restrict__ bq,
           const float* __restrict__ Wk,   const float* __restrict__ bk,
           const float* __restrict__ Wav,  const float* __restrict__ bav,
           const float* __restrict__ Wfv,  const float* __restrict__ bfv,
           const float* __restrict__ W1,   const float* __restrict__ b1,
           const float* __restrict__ W2,   const float* __restrict__ W1o,
           const float* __restrict__ b2,   const float* __restrict__ b1o,
           float* __restrict__ out_attnw)
{
    extern __shared__ float sm[];
    int bx = blockIdx.x;
    int t  = threadIdx.x;

    if (bx < 128) {
        // ---- M = W2 @ W1o, c1 ----  (one block per SM in slot 1)
        int id = bx;
        int kb = (id & 1) * 128;
        int cb = ((id >> 1) & 1) * 128;
        int h  = id >> 2;

        float* As = sm;              // [128][33]
        float* Bs = As + 128 * 33;   // [32][132]
        const float* Ap = W2  + (size_t)h * HID * VD;
        const float* Bp = W1o + (size_t)h * VD * HID;

        int ty = t >> 4, tx = t & 15;
        F2 acc[8][4];
#pragma unroll
        for (int r = 0; r < 8; r++)
#pragma unroll
            for (int j = 0; j < 4; j++) acc[r][j] = zero2();

        for (int vc = 0; vc < VD; vc += 32) {
            __syncthreads();
            {
                int row = t >> 5, col = t & 31;
#pragma unroll
                for (int rr = 0; rr < 16; rr++)
                    As[(row + rr * 8) * 33 + col] = Ap[(size_t)(kb + row + rr * 8) * VD + vc + col];
            }
#pragma unroll
            for (int i = 0; i < 16; i++) {
                int idx = t + i * 256;
                int vr = idx >> 7, col = idx & 127;
                Bs[vr * 132 + col] = Bp[(size_t)(vc + vr) * HID + cb + col];
            }
            __syncthreads();
#pragma unroll
            for (int v = 0; v < 32; v++) {
                F2 bvec[4];
#pragma unroll
                for (int j = 0; j < 4; j++) bvec[j] = lds2(&Bs[v * 132 + tx * 2 + 32 * j]);
#pragma unroll
                for (int r = 0; r < 8; r++) {
                    F2 a2 = bcast2(As[(ty * 8 + r) * 33 + v]);
#pragma unroll
                    for (int j = 0; j < 4; j++) acc[r][j] = ffma2(a2, bvec[j], acc[r][j]);
                }
            }
        }

        float* Mp = g_M + (size_t)h * HID * HID;
#pragma unroll
        for (int r = 0; r < 8; r++)
#pragma unroll
            for (int j = 0; j < 4; j++)
                *(unsigned long long*)&Mp[(size_t)(kb + ty * 8 + r) * HID + cb + tx * 2 + 32 * j] = acc[r][j].u;

        if ((id & 1) == 0 && t < 128) {
            int kp = cb + t;
            float c = b1o[h * HID + kp];
            for (int v = 0; v < VD; v++)
                c = fmaf(b2[h * VD + v], Bp[(size_t)v * HID + kp], c);
            g_c1[h * HID + kp] = c;
        }

    } else if (bx < 192) {
        // ---- prep: one warp per batch ----
        float* Wk_s = sm;               // [32][193] = 6176
        float* q_s  = sm + 6176;        // [8][192]
        int wid = t >> 5, lane = t & 31;
        int b = (bx - 128) * 8 + wid;

        for (int idx = t; idx < DLAT * KDIM; idx += 256) {
            int d = idx / KDIM, j = idx - d * KDIM;
            Wk_s[d * 193 + j] = Wk[idx];
        }

        float av = (lane < ACT) ? act[b * ACT + lane] : 0.f;
        float q[6];
#pragma unroll
        for (int m = 0; m < 6; m++) q[m] = bq[m * 32 + lane];
#pragma unroll
        for (int i = 0; i < ACT; i++) {
            float ai = __shfl_sync(0xffffffffu, av, i);
#pragma unroll
            for (int m = 0; m < 6; m++)
                q[m] = fmaf(ai, Wq[i * KDIM + m * 32 + lane], q[m]);
        }
#pragma unroll
        for (int m = 0; m < 6; m++) q_s[wid * 192 + m * 32 + lane] = q[m];
        __syncthreads();

        const float* qs = q_s + wid * 192;
        float s1 = 0.f;
#pragma unroll 6
        for (int j = 0; j < KDIM; j++) s1 = fmaf(Wk_s[lane * 193 + j], qs[j], s1);
        float s0 = 0.f;
#pragma unroll
        for (int m = 0; m < 6; m++) s0 = fmaf(bk[lane * 6 + m], qs[lane * 6 + m], s0);
#pragma unroll
        for (int o = 16; o > 0; o >>= 1) s0 += __shfl_xor_sync(0xffffffffu, s0, o);

        const float inv = 0.07216878364870323f; // 1/sqrt(192)
        float sc = (feat[b * DLAT + lane] * s1 + s0) * inv;
        float m = sc;
#pragma unroll
        for (int o = 16; o > 0; o >>= 1) m = fmaxf(m, __shfl_xor_sync(0xffffffffu, m, o));
        float e = __expf(sc - m);
        float s = e;
#pragma unroll
        for (int o = 16; o > 0; o >>= 1) s += __shfl_xor_sync(0xffffffffu, s, o);
        float w = e / s;
        g_w[b * DLAT + lane] = w;
#pragma unroll 8
        for (int hh = 0; hh < NH; hh++)
            out_attnw[(size_t)b * NH * DLAT + hh * DLAT + lane] = w;

    } else if (bx < 256) {
        // ---- G + c0 ----
        int bxg = bx - 192;
        int h  = bxg >> 1;
        int d0 = (bxg & 1) * 16;
        float* WfvT  = sm;              // [128 f][36 pad]
        float* bfv_s = sm + FED * 36;   // 128
        for (int r = 0; r < DLAT; r++) {
            for (int f = t; f < FED; f += 256) WfvT[f * 36 + r] = Wfv[r * FED + f];
        }
        if (t < FED) bfv_s[t] = bfv[t];
        __syncthreads();

        const float* W1h = W1 + (size_t)h * VD * HID;
        float acc[16] = {};
        float c0a = (d0 == 0) ? b1[h * HID + t] : 0.f;
#pragma unroll 4
        for (int f = 0; f < FED; f++) {
            float v = W1h[(size_t)f * HID + t];
            if (d0 == 0) c0a = fmaf(bfv_s[f], v, c0a);
            const float* wf = &WfvT[f * 36 + d0];
#pragma unroll
            for (int d = 0; d < 16; d++) acc[d] = fmaf(wf[d], v, acc[d]);
        }
#pragma unroll
        for (int d = 0; d < 16; d++)
            g_G[((size_t)h * DLAT + d0 + d) * HID + t] = acc[d];
        if (d0 == 0) g_c0[h * HID + t] = c0a;

    } else {
        // ---- TT[h,i,k] = sum_a Wav[i,a] W1a[h,a,k];  c2 = sum_a bav[a] W1a ----
        int h = bx - 256;
        float* WavS = sm;               // [18][64] = 1152
        float* bavS = sm + 1152;        // 64
        for (int idx = t; idx < ACT * AED; idx += 256) WavS[idx] = Wav[idx];
        if (t < AED) bavS[t] = bav[t];
        __syncthreads();

        const float* W1a = W1 + (size_t)h * VD * HID + (size_t)FED * HID;
        float acc[ACT] = {};
        float c2 = 0.f;
#pragma unroll 2
        for (int a = 0; a < AED; a++) {
            float v = W1a[(size_t)a * HID + t];        // coalesced LDG
            c2 = fmaf(bavS[a], v, c2);
#pragma unroll
            for (int i = 0; i < ACT; i++)
                acc[i] = fmaf(WavS[i * AED + a], v, acc[i]);
        }
#pragma unroll
        for (int i = 0; i < ACT; i++)
            g_TT[((size_t)h * ACT + i) * HID + t] = acc[i];
        g_c2[h * HID + t] = c2;
    }
}

// ============================================================================
// K2 (fused E+pool+out): grid (8, 32), 256 threads, 2 CTAs/SM.  (R14 winner,
// byte-identical — at its FFMA2 issue ceiling, do not touch.)
// Phase 1: e0 = act@TT (rank-18) + c0 + c2; P = sum_d w*relu(z*G + e0).
// Phase 2: GEMM P[64,256] @ M[256,256], dbl-buffered 16-row M chunks.
// smem: P 16384 | R 8448 (Gb 2048 + zw 4096 + TTp 1152 + actS 1152
//       <-> ph2 M dblbuf 2x4096) | cw 512 | c0 256 = 25600f = 102400B
// ============================================================================
__global__ __launch_bounds__(256, 2)
void k_fused(const float* __restrict__ feat, const float* __restrict__ act,
             const float* __restrict__ W2o,  const float* __restrict__ b2o,
             float* __restrict__ effect)
{
    int h  = blockIdx.y;
    int b0 = blockIdx.x * 64;
    int t  = threadIdx.x;
    int tb = t >> 4, tk = t & 15;     // 16 row-groups x 16 lanes

    extern __shared__ float sm[];
    float* P_s  = sm;                 // [64][256]
    float* R    = sm + 16384;         // 8448f overlay
    float* Gb   = R;                  // ph1: Gbuf [32][64]   (2048f)
    float* zw   = R + 2048;           // ph1: zw [64][32] f2  (4096f)
    float* TTp  = R + 6144;           // ph1: TT slice [18][64] (1152f)
    float* actS = R + 7296;           // ph1: act [64][18]    (1152f)
    float* cw   = sm + 16384 + 8448;  // ph2: c1 [256] + W2o [256]
    float* c0s  = cw + 512;           // c0 + c2 [256]

    // ---- phase 1 static loads ----
    for (int idx = t; idx < 64 * DLAT; idx += 256) {
        int row = idx >> 5, d = idx & 31;
        zw[idx * 2 + 0] = feat[(b0 + row) * DLAT + d];
        zw[idx * 2 + 1] = g_w[(b0 + row) * DLAT + d];
    }
    for (int idx = t; idx < 64 * ACT; idx += 256) {
        int row = idx / ACT, i = idx - row * ACT;
        actS[idx] = act[(b0 + row) * ACT + i];
    }
    if (t < HID) c0s[t] = g_c0[h * HID + t] + g_c2[h * HID + t];

    const float* Gp  = g_G  + (size_t)h * DLAT * HID;
    const float* TTh = g_TT + (size_t)h * ACT * HID;

    // ---- phase 1: 4 column passes of 64 cols ----
#pragma unroll 1
    for (int p = 0; p < 4; p++) {
        int cb = p * 64;
        __syncthreads();
#pragma unroll
        for (int i = 0; i < 2; i++) {          // Gbuf: 512 float4 / 256 thr
            int idx = t + i * 256;
            int d = idx >> 4, c4 = idx & 15;
            ((float4*)Gb)[idx] = *(const float4*)&Gp[d * HID + cb + c4 * 4];
        }
        {                                       // TT slice: 288 float4
            int idx = t;
            int ii = idx >> 4, c4 = idx & 15;
            ((float4*)TTp)[idx] = *(const float4*)&TTh[(size_t)ii * HID + cb + c4 * 4];
            idx = t + 256;
            if (idx < ACT * 16) {
                ii = idx >> 4; c4 = idx & 15;
                ((float4*)TTp)[idx] = *(const float4*)&TTh[(size_t)ii * HID + cb + c4 * 4];
            }
        }
        __syncthreads();

        int lc = tk * 2;
        // e0 = c0+c2 + act @ TT  (rank-18)
        F2 e0[4][2], acc[4][2];
#pragma unroll
        for (int r = 0; r < 4; r++)
#pragma unroll
            for (int i = 0; i < 2; i++) {
                e0[r][i] = lds2(&c0s[cb + lc + 32 * i]);
                acc[r][i] = zero2();
            }
#pragma unroll 2
        for (int ii = 0; ii < ACT; ii++) {
            F2 tt[2];
#pragma unroll
            for (int i = 0; i < 2; i++) tt[i] = lds2(&TTp[ii * 64 + lc + 32 * i]);
#pragma unroll
            for (int r = 0; r < 4; r++) {
                F2 av = bcast2(actS[(tb * 4 + r) * ACT + ii]);
#pragma unroll
                for (int i = 0; i < 2; i++) e0[r][i] = ffma2(av, tt[i], e0[r][i]);
            }
        }

#pragma unroll 4
        for (int d = 0; d < DLAT; d++) {
            F2 gr[2];
#pragma unroll
            for (int i = 0; i < 2; i++) gr[i] = lds2(&Gb[d * 64 + lc + 32 * i]);
#pragma unroll
            for (int r = 0; r < 4; r++) {
                float2 z = *(const float2*)&zw[((tb * 4 + r) * DLAT + d) * 2];
                F2 z2 = bcast2(z.x), w2 = bcast2(z.y);
#pragma unroll
                for (int i = 0; i < 2; i++) {
                    F2 u = ffma2(z2, gr[i], e0[r][i]);
                    u.f.x = fmaxf(u.f.x, 0.f);
                    u.f.y = fmaxf(u.f.y, 0.f);
                    acc[r][i] = ffma2(w2, u, acc[r][i]);
                }
            }
        }

#pragma unroll
        for (int r = 0; r < 4; r++)
#pragma unroll
            for (int i = 0; i < 2; i++)
                *(unsigned long long*)&P_s[(tb * 4 + r) * HID + cb + lc + 32 * i] = acc[r][i].u;
    }
    __syncthreads();   // phase 1 done; R free

    // ---- phase 2 loads: c1 + W2o, M chunk 0 into R[0] ----
    if (t < HID) {
        cw[t]       = g_c1[h * HID + t];
        cw[HID + t] = W2o[h * HID + t];
    }
    const float* Mp = g_M + (size_t)h * HID * HID;
#pragma unroll
    for (int i = 0; i < 4; i++)        // chunk 0: 16 rows = 1024 float4
        ((float4*)R)[t + i * 256] = ((const float4*)Mp)[t + i * 256];
    __syncthreads();

    // ---- phase 2: GEMM, 16 k-chunks, dbl-buffered (1 sync/chunk) ----
    F2 acc[4][8];
#pragma unroll
    for (int r = 0; r < 4; r++)
#pragma unroll
        for (int j = 0; j < 8; j++) acc[r][j] = zero2();

#pragma unroll 1
    for (int kc = 0; kc < 16; kc++) {
        float4 pf[4];
        if (kc < 15) {
#pragma unroll
            for (int i = 0; i < 4; i++)
                pf[i] = ((const float4*)(Mp + (size_t)(kc + 1) * 16 * HID))[t + i * 256];
        }
        const float* Mc = R + (kc & 1) * 4096;
#pragma unroll
        for (int kk = 0; kk < 16; kk++) {
            int k = kc * 16 + kk;
            F2 mv[8];
#pragma unroll
            for (int j = 0; j < 8; j++) mv[j] = lds2(&Mc[kk * HID + tk * 2 + 32 * j]);
#pragma unroll
            for (int r = 0; r < 4; r++) {
                F2 p2 = bcast2(P_s[(tb * 4 + r) * HID + k]);
#pragma unroll
                for (int j = 0; j < 8; j++) acc[r][j] = ffma2(p2, mv[j], acc[r][j]);
            }
        }
        if (kc < 15) {
            float* dst = R + ((kc + 1) & 1) * 4096;
#pragma unroll
            for (int i = 0; i < 4; i++)
                ((float4*)dst)[t + i * 256] = pf[i];
        }
        __syncthreads();
    }

    // ---- epilogue: +c1, relu, dot W2o, reduce over tk (16 lanes) ----
    float part[4];
#pragma unroll
    for (int r = 0; r < 4; r++) {
        float s = 0.f;
#pragma unroll
        for (int j = 0; j < 8; j++) {
            int c = tk * 2 + 32 * j;
            float hx = fmaxf(acc[r][j].f.x + cw[c], 0.f);
            float hy = fmaxf(acc[r][j].f.y + cw[c + 1], 0.f);
            s = fmaf(hx, cw[HID + c], s);
            s = fmaf(hy, cw[HID + c + 1], s);
        }
        part[r] = s;
    }
#pragma unroll
    for (int o = 8; o > 0; o >>= 1)
#pragma unroll
        for (int r = 0; r < 4; r++)
            part[r] += __shfl_xor_sync(0xffffffffu, part[r], o);

    if (tk == 0) {
        float bo = b2o[h];
#pragma unroll
        for (int r = 0; r < 4; r++)
            effect[(size_t)(b0 + tb * 4 + r) * NH + h] = part[r] + bo;
    }
}

// ============================================================================
extern "C" void kernel_launch(void* const* d_in, const int* in_sizes, int n_in,
                              void* d_out, int out_size)
{
    const float* feat = (const float*)d_in[0];
    const float* act  = (const float*)d_in[1];
    const float* Wq   = (const float*)d_in[2];
    const float* bq   = (const float*)d_in[3];
    const float* Wk   = (const float*)d_in[4];
    const float* bk   = (const float*)d_in[5];
    const float* Wav  = (const float*)d_in[6];
    const float* bav  = (const float*)d_in[7];
    const float* Wfv  = (const float*)d_in[8];
    const float* bfv  = (const float*)d_in[9];
    const float* W1   = (const float*)d_in[10];
    const float* b1   = (const float*)d_in[11];
    const float* W2   = (const float*)d_in[12];
    const float* b2   = (const float*)d_in[13];
    const float* W1o  = (const float*)d_in[14];
    const float* b1o  = (const float*)d_in[15];
    const float* W2o  = (const float*)d_in[16];
    const float* b2o  = (const float*)d_in[17];

    float* out    = (float*)d_out;
    float* effect = out;                    // [B, H]
    float* attnw  = out + BATCH * NH;       // [B, H, D]

    int smem1 = (128 * 33 + 32 * 132) * 4;                       // 33792 (M branch = max)
    int smem2 = (16384 + 8448 + 512 + 256) * 4;                  // 102400
    cudaFuncSetAttribute(k_pre,   cudaFuncAttributeMaxDynamicSharedMemorySize, smem1);
    cudaFuncSetAttribute(k_fused, cudaFuncAttributeMaxDynamicSharedMemorySize, smem2);

    k_pre<<<288, 256, smem1>>>(feat, act, Wq, bq, Wk, bk, Wav, bav,
                               Wfv, bfv, W1, b1, W2, W1o, b2, b1o, attnw);
    k_fused<<<dim3(BATCH / 64, NH), 256, smem2>>>(feat, act, W2o, b2o, effect);
}